// round 15
// baseline (speedup 1.0000x reference)
#include <cuda_runtime.h>
#include <math.h>

// Problem constants
#define Bc 32
#define Nc 256
#define Tc 64
#define Mc 64
#define Hc 512
#define Wc 512
#define COL_THRESH 0.5f

#define GRP 32                      // threads per candidate = one warp
#define T_PER_THR 2                 // timesteps per thread (GRP*T_PER_THR = Tc)
#define CAND_PER_BLK 8              // candidates per 256-thread block
#define THREADS 256
#define BLKS_PER_B (Nc / CAND_PER_BLK)   // 32 blocks per batch -> 1024 blocks

// Scratch for raw per-(b,n) scores: [f_dis, f_pg, min_col_sq, f_dac]
__device__ float4 g_scratch[Bc * Nc];
// Per-batch completion counters (zero-initialized; reset by the winner)
__device__ int g_cnt[Bc];

// ---------------------------------------------------------------------------
// Fused kernel. grid = (32, B), block = 256 threads — 1024 blocks, ~85% occ.
// Phase 1: one WARP per candidate, 2 timesteps per thread; reduction is a
//          pure warp shuffle. High warp count hides LDS/DRAM latency.
// Phase 2: the LAST block per batch normalizes, argmaxes, copies best traj.
// ---------------------------------------------------------------------------
__global__ __launch_bounds__(THREADS) void fused_kernel(
    const float* __restrict__ traj,     // (B,N,T,2)
    const float* __restrict__ goal,     // (B,2)
    const float* __restrict__ gt,       // (B,T,2)
    const float* __restrict__ obs,      // (B,M,2)
    const float* __restrict__ da,       // (B,H,W)
    float* __restrict__ out)            // [B*T*2 best | B*N scores]
{
    const int b   = blockIdx.y;
    const int tid = threadIdx.x;
    const int c   = tid >> 5;                       // candidate slot 0..7
    const int tg  = tid & 31;                       // lane in candidate warp
    const int n   = blockIdx.x * CAND_PER_BLK + c;  // candidate index
    const int t0  = tg * T_PER_THR;                 // first timestep

    __shared__ float4 s_obs[Mc];   // (-2*ox, -2*oy, |o|^2, pad)
    __shared__ int    s_last;

    // ===== Phase 0: cheap L2 warming of this block's slice of da[b] =====
    // 1024-block grid: block x warms floats [x*8192,(x+1)*8192), one float
    // per 32B sector, warp-contiguous (streaming-friendly).
    {
        const float* wbase = da + (size_t)b * (Hc * Wc) + blockIdx.x * 8192;
        float wsum = 0.0f;
#pragma unroll
        for (int k = 0; k < 4; k++)
            wsum += __ldcg(wbase + (((k * THREADS) + tid) << 3));
        asm volatile("" :: "f"(wsum));   // keep the loads alive
    }

    // ===== FRONT-BATCHED LOADS =====

    // my 2 trajectory points (1x float4, coalesced)
    const float4* traj4 = (const float4*)traj;
    float4 q = traj4[((b * Nc + n) * Tc + t0) >> 1];

    // gt points (batch-broadcast, cached)
    const float4* gt4 = (const float4*)gt;
    float4 G = __ldg(&gt4[(b * Tc + t0) >> 1]);

    // goal (endpoint-owner lane only)
    float2 gl = make_float2(0.0f, 0.0f);
    if (tg == GRP - 1) gl = ((const float2*)goal)[b];

    // obstacle prefetch into registers (first 64 threads)
    float2 opre = make_float2(0.0f, 0.0f);
    if (tid < Mc) opre = ((const float2*)obs)[b * Mc + tid];

    float px[2] = {q.x, q.z};
    float py[2] = {q.y, q.w};

    // ===== DAC gathers issued early so latency hides under the loop =====
    float dval[2];
#pragma unroll
    for (int j = 0; j < 2; j++) {
        int xi = (int)((px[j] + 50.0f) / 100.0f * (float)(Wc - 1));
        int yi = (int)((py[j] + 50.0f) / 100.0f * (float)(Hc - 1));
        xi = min(max(xi, 0), Wc - 1);
        yi = min(max(yi, 0), Hc - 1);
        dval[j] = __ldg(&da[(size_t)b * (Hc * Wc) + yi * Wc + xi]);
    }

    // stage transformed obstacles into shared
    if (tid < Mc) {
        float o2 = fmaf(opre.x, opre.x, opre.y * opre.y);
        s_obs[tid] = make_float4(-2.0f * opre.x, -2.0f * opre.y, o2, 0.0f);
    }

    // --- distance-to-GT while the STS drains ---
    float dis;
    {
        float dx0 = px[0] - G.x, dy0 = py[0] - G.y;
        float dx1 = px[1] - G.z, dy1 = py[1] - G.w;
        dis = sqrtf(fmaf(dx0, dx0, dy0 * dy0)) +
              sqrtf(fmaf(dx1, dx1, dy1 * dy1));
    }

    // --- progress term (endpoint owner only) ---
    float pg = 0.0f;
    if (tg == GRP - 1) {
        float ex = px[1] - gl.x, ey = py[1] - gl.y;
        pg = sqrtf(fmaf(ex, ex, ey * ey));
    }

    __syncthreads();   // obstacles visible

    // --- collision: min over M of (|o|^2 - 2 p.o) per point; 7 instr/iter ---
    const float BIG = 3.402823466e+38f;
    float mc0 = BIG, mc1 = BIG;
#pragma unroll 8
    for (int m = 0; m < Mc; m++) {
        float4 o = s_obs[m];       // broadcast, conflict-free
        mc0 = fminf(mc0, fmaf(py[0], o.y, fmaf(px[0], o.x, o.z)));
        mc1 = fminf(mc1, fmaf(py[1], o.y, fmaf(px[1], o.x, o.z)));
    }
    float mind2 = fminf(fmaf(px[0], px[0], py[0] * py[0]) + mc0,
                        fmaf(px[1], px[1], py[1] * py[1]) + mc1);
    mind2 = fmaxf(mind2, 0.0f);    // clamp commutes with min; guard sqrt later

    // --- consume DAC gathers ---
    float dac = (1.0f - dval[0]) + (1.0f - dval[1]);

    // --- full-warp reduction (candidate group == warp) ---
#pragma unroll
    for (int off = 16; off > 0; off >>= 1) {
        dis   += __shfl_xor_sync(0xFFFFFFFFu, dis, off);
        dac   += __shfl_xor_sync(0xFFFFFFFFu, dac, off);
        pg    += __shfl_xor_sync(0xFFFFFFFFu, pg, off);
        mind2  = fminf(mind2, __shfl_xor_sync(0xFFFFFFFFu, mind2, off));
    }
    if (tg == 0) {
        g_scratch[b * Nc + n] =
            make_float4(dis * (1.0f / Tc), pg, mind2, dac * (1.0f / Tc));
        __threadfence();   // storer fences its own write before block signal
    }
    __syncthreads();

    // ---- completion signalling: last block for this batch does the select ---
    if (tid == 0) {
        int old = atomicAdd(&g_cnt[b], 1);
        s_last = (old == BLKS_PER_B - 1) ? 1 : 0;
    }
    __syncthreads();
    if (!s_last) return;
    __threadfence();                          // acquire others' scratch writes

    // =======================================================================
    // Phase 2 (one block per batch): 256 threads, 1 candidate per thread.
    // Block-level warp indices (0..7) — proven R12 form.
    // =======================================================================
    {
        const int nn    = tid;
        const int lane2 = tid & 31;
        const int w2    = tid >> 5;   // 0..7

        __shared__ float s_mn[8][4], s_mx[8][4];
        __shared__ float s_fmn[4], s_fmx[4];
        __shared__ float s_bs[8];
        __shared__ int   s_bi[8];
        __shared__ int   s_best;

        // L2-coherent read of all candidates' raw scores for this batch
        const float4* sc = &g_scratch[b * Nc + nn];
        float4 raw;
        raw.x = __ldcg(&sc->x);
        raw.y = __ldcg(&sc->y);
        raw.z = __ldcg(&sc->z);
        raw.w = __ldcg(&sc->w);

        float mcol = sqrtf(raw.z);
        float ttv  = mcol - COL_THRESH;
        float v[4];
        v[0] = raw.x;               // f_dis
        v[1] = raw.y;               // f_pg
        v[2] = expf(-(ttv * ttv));  // f_col
        v[3] = raw.w;               // f_dac

        // --- combined 8-value reduction (4 mins + 4 maxes) ---
        float mn4[4], mx4[4];
#pragma unroll
        for (int i = 0; i < 4; i++) { mn4[i] = v[i]; mx4[i] = v[i]; }
#pragma unroll
        for (int off = 16; off > 0; off >>= 1) {
#pragma unroll
            for (int i = 0; i < 4; i++) {
                mn4[i] = fminf(mn4[i], __shfl_xor_sync(0xFFFFFFFFu, mn4[i], off));
                mx4[i] = fmaxf(mx4[i], __shfl_xor_sync(0xFFFFFFFFu, mx4[i], off));
            }
        }
        if (lane2 == 0) {
#pragma unroll
            for (int i = 0; i < 4; i++) { s_mn[w2][i] = mn4[i]; s_mx[w2][i] = mx4[i]; }
        }
        __syncthreads();
        if (w2 == 0) {   // full warp participates — convergent shuffles
#pragma unroll
            for (int i = 0; i < 4; i++) {
                mn4[i] = s_mn[lane2 & 7][i];
                mx4[i] = s_mx[lane2 & 7][i];
            }
#pragma unroll
            for (int off = 4; off > 0; off >>= 1) {
#pragma unroll
                for (int i = 0; i < 4; i++) {
                    mn4[i] = fminf(mn4[i], __shfl_xor_sync(0xFFFFFFFFu, mn4[i], off));
                    mx4[i] = fmaxf(mx4[i], __shfl_xor_sync(0xFFFFFFFFu, mx4[i], off));
                }
            }
            if (lane2 == 0) {
#pragma unroll
                for (int i = 0; i < 4; i++) { s_fmn[i] = mn4[i]; s_fmx[i] = mx4[i]; }
            }
        }
        __syncthreads();

        float score = 0.0f;
#pragma unroll
        for (int i = 0; i < 4; i++) {
            float d = s_fmx[i] - s_fmn[i];
            d = (d == 0.0f) ? 1.0f : d;
            score += (v[i] - s_fmn[i]) / d;
        }
        score = -score;

        // scores output region follows the best_trajectory block
        float* out_scores = out + (Bc * Tc * 2);
        out_scores[b * Nc + nn] = score;

        // --- argmax with first-index tie-break (matches jnp.argmax) ---
        float bs = score;
        int   bi = nn;
#pragma unroll
        for (int off = 16; off > 0; off >>= 1) {
            float os = __shfl_xor_sync(0xFFFFFFFFu, bs, off);
            int   oi = __shfl_xor_sync(0xFFFFFFFFu, bi, off);
            if (os > bs || (os == bs && oi < bi)) { bs = os; bi = oi; }
        }
        if (lane2 == 0) { s_bs[w2] = bs; s_bi[w2] = bi; }
        __syncthreads();
        if (w2 == 0) {   // full warp participates — convergent shuffles
            bs = s_bs[lane2 & 7];
            bi = s_bi[lane2 & 7];
#pragma unroll
            for (int off = 4; off > 0; off >>= 1) {
                float os = __shfl_xor_sync(0xFFFFFFFFu, bs, off);
                int   oi = __shfl_xor_sync(0xFFFFFFFFu, bi, off);
                if (os > bs || (os == bs && oi < bi)) { bs = os; bi = oi; }
            }
            if (lane2 == 0) s_best = bi;
        }
        __syncthreads();

        // --- copy best trajectory: T*2 = 128 floats = 64 float2 ---
        const int best = s_best;
        if (tid < Tc) {
            ((float2*)out)[b * Tc + tid] =
                ((const float2*)traj)[((size_t)(b * Nc + best)) * Tc + tid];
        }

        // reset counter for the next graph replay (all arrivals already in)
        if (tid == 0) g_cnt[b] = 0;
    }
}

// ---------------------------------------------------------------------------
// Launch
// ---------------------------------------------------------------------------
extern "C" void kernel_launch(void* const* d_in, const int* in_sizes, int n_in,
                              void* d_out, int out_size)
{
    const float* traj = (const float*)d_in[0];   // (B,N,T,2)
    const float* goal = (const float*)d_in[1];   // (B,2)
    const float* gt   = (const float*)d_in[2];   // (B,T,2)
    const float* obs  = (const float*)d_in[3];   // (B,M,2)
    const float* da   = (const float*)d_in[4];   // (B,H,W)
    float* out = (float*)d_out;

    dim3 g1(BLKS_PER_B, Bc);
    fused_kernel<<<g1, THREADS>>>(traj, goal, gt, obs, da, out);
}